// round 14
// baseline (speedup 1.0000x reference)
#include <cuda_runtime.h>
#include <cuda_bf16.h>

// Problem constants
#define BS1 32
#define BS2 128
#define NUM_EC 64
#define MEM_DIM 256
#define MLP_DIM 256
#define Q_DIM 256           // 4 * CONV_DIM

// Scratch (device globals — allocation is forbidden)
__device__ float g_att[BS1 * NUM_EC];              // softmax_e(criteria·Wa_c)
__device__ float g_PC [BS1 * NUM_EC * MLP_DIM];    // raw criteria @ Wm_c
__device__ float g_PE [BS2 * MLP_DIM];             // ehr @ Wm_e

// ---- PDL primitives ----
__device__ __forceinline__ void pdl_trigger() {
    asm volatile("griddepcontrol.launch_dependents;");
}
__device__ __forceinline__ void pdl_wait() {
    asm volatile("griddepcontrol.wait;" ::: "memory");
}

// ---- packed f32x2 helpers ----
__device__ __forceinline__ unsigned long long pk2(float lo, float hi) {
    unsigned long long r;
    asm("mov.b64 %0, {%1, %2};" : "=l"(r)
        : "r"(__float_as_uint(lo)), "r"(__float_as_uint(hi)));
    return r;
}
__device__ __forceinline__ unsigned long long fma2(unsigned long long a,
                                                   unsigned long long b,
                                                   unsigned long long c) {
    unsigned long long d;
    asm("fma.rn.f32x2 %0, %1, %2, %3;" : "=l"(d) : "l"(a), "l"(b), "l"(c));
    return d;
}
__device__ __forceinline__ float2 upk2(unsigned long long v) {
    unsigned int lo, hi;
    asm("mov.b64 {%0, %1}, %2;" : "=r"(lo), "=r"(hi) : "l"(v));
    return make_float2(__uint_as_float(lo), __uint_as_float(hi));
}

// ---- 256-bit global ld/st (PTX ISA 8.8, sm_100+) ----
struct f8 { float4 a, b; };
__device__ __forceinline__ f8 ldg256(const float* p) {
    f8 r;
    asm volatile("ld.global.nc.v8.f32 {%0,%1,%2,%3,%4,%5,%6,%7}, [%8];"
        : "=f"(r.a.x), "=f"(r.a.y), "=f"(r.a.z), "=f"(r.a.w),
          "=f"(r.b.x), "=f"(r.b.y), "=f"(r.b.z), "=f"(r.b.w)
        : "l"(p));
    return r;
}
__device__ __forceinline__ void stg256_cs(float* p, const f8& v) {
    asm volatile("st.global.cs.v8.f32 [%0], {%1,%2,%3,%4,%5,%6,%7,%8};"
        :: "l"(p),
           "f"(v.a.x), "f"(v.a.y), "f"(v.a.z), "f"(v.a.w),
           "f"(v.b.x), "f"(v.b.y), "f"(v.b.z), "f"(v.b.w)
        : "memory");
}

// ---------------------------------------------------------------------------
// Prep kernel, 320 blocks (R10 config, best measured):
//   bids [0,256):   PC[b,e,d] = dot(criteria[b,e,:], Wm_c[:,d])
//     Block = (b, e-tile of 16, d-half of 128); thread = (4d, 4e, k-half).
//     FMA2 paired across d; W float4 rows give packs free.
//   bids [256,288): att[b,:] = softmax_e(criteria[b,e,:]·Wa_c)
//                   (logit_e[p] and b_align are constant over e -> cancel)
//   bids [288,320): PE[p,d] = dot(ehr[p,:], Wm_e[:,d])   (4 p / block)
// ---------------------------------------------------------------------------
#define C1_BLOCKS   256
#define ATT_BLOCKS  32
#define PE_BLOCKS   32
#define E_TILE      16
#define PE_P_TILE   4

__global__ void __launch_bounds__(256) k_prep(const float* __restrict__ ehr,
                                              const float* __restrict__ crit,
                                              const float* __restrict__ W_align,
                                              const float* __restrict__ W_mlp) {
    __shared__ __align__(16) float sbuf[E_TILE * Q_DIM];   // 16 KB, reused
    const int bid = blockIdx.x;
    const int tid = threadIdx.x;

    if (bid < C1_BLOCKS) {
        // ----- PC -----
        const int b   = bid >> 3;
        const int et  = (bid >> 1) & 3;
        const int dh  = bid & 1;
        const int e0  = et * E_TILE;
        const int dg  = tid & 31;          // d-group (4 d each)
        const int es  = (tid >> 5) & 3;    // e-subtile (4 e each)
        const int kh  = tid >> 7;          // k-half (0/1)
        const int dloc = dg * 4;           // d within the 128-wide half
        const int d0  = dh * 128 + dloc;   // global d

        // load criteria[b, e0..e0+15, 0..255]  (1024 float4, 4 per thread)
        float4* cs = (float4*)sbuf;        // [E_TILE][64]
        const float4* src = (const float4*)(crit + (size_t)(b * NUM_EC + e0) * Q_DIM);
        #pragma unroll
        for (int i = 0; i < 4; ++i)
            cs[tid + i * 256] = src[tid + i * 256];
        __syncthreads();

        unsigned long long acc01[4], acc23[4];
        #pragma unroll
        for (int e = 0; e < 4; ++e) { acc01[e] = 0ull; acc23[e] = 0ull; }

        const int k4base = kh * 32;
        #pragma unroll 2
        for (int j = 0; j < 32; ++j) {
            const int k4 = k4base + j;
            const int k  = k4 * 4;
            const float4 w0 = *(const float4*)(W_mlp + (size_t)(k + 0) * MLP_DIM + d0);
            const float4 w1 = *(const float4*)(W_mlp + (size_t)(k + 1) * MLP_DIM + d0);
            const float4 w2 = *(const float4*)(W_mlp + (size_t)(k + 2) * MLP_DIM + d0);
            const float4 w3 = *(const float4*)(W_mlp + (size_t)(k + 3) * MLP_DIM + d0);
            const unsigned long long w0a = pk2(w0.x, w0.y), w0b = pk2(w0.z, w0.w);
            const unsigned long long w1a = pk2(w1.x, w1.y), w1b = pk2(w1.z, w1.w);
            const unsigned long long w2a = pk2(w2.x, w2.y), w2b = pk2(w2.z, w2.w);
            const unsigned long long w3a = pk2(w3.x, w3.y), w3b = pk2(w3.z, w3.w);
            #pragma unroll
            for (int e = 0; e < 4; ++e) {
                const float4 c = cs[(es * 4 + e) * 64 + k4];  // broadcast LDS.128
                unsigned long long cx = pk2(c.x, c.x);
                unsigned long long cy = pk2(c.y, c.y);
                unsigned long long cz = pk2(c.z, c.z);
                unsigned long long cw = pk2(c.w, c.w);
                acc01[e] = fma2(cx, w0a, acc01[e]);
                acc23[e] = fma2(cx, w0b, acc23[e]);
                acc01[e] = fma2(cy, w1a, acc01[e]);
                acc23[e] = fma2(cy, w1b, acc23[e]);
                acc01[e] = fma2(cz, w2a, acc01[e]);
                acc23[e] = fma2(cz, w2b, acc23[e]);
                acc01[e] = fma2(cw, w3a, acc01[e]);
                acc23[e] = fma2(cw, w3b, acc23[e]);
            }
        }
        __syncthreads();                   // criteria consumed; reuse as partials

        // partials: [2 kh][16 e][128 dloc]  = 16 KB
        float* part = sbuf;
        #pragma unroll
        for (int e = 0; e < 4; ++e) {
            const float2 a = upk2(acc01[e]);
            const float2 b2 = upk2(acc23[e]);
            float* p = part + ((kh * E_TILE + es * 4 + e) * 128 + dloc);
            p[0] = a.x; p[1] = a.y; p[2] = b2.x; p[3] = b2.y;
        }
        __syncthreads();

        // 2048 outputs, 256 threads -> 8 each (coalesced over dd)
        #pragma unroll
        for (int i = 0; i < 8; ++i) {
            const int idx = tid + i * 256;         // e*128 + dd
            const int e  = idx >> 7;
            const int dd = idx & 127;
            float v = part[e * 128 + dd] + part[(E_TILE + e) * 128 + dd];
            g_PC[((size_t)(b * NUM_EC + e0 + e)) * MLP_DIM + dh * 128 + dd] = v;
        }
        pdl_trigger();

    } else if (bid < C1_BLOCKS + ATT_BLOCKS) {
        // ----- att -----
        const int b = bid - C1_BLOCKS;
        const int e = tid >> 2;
        const int q = tid & 3;

        const float4* row = (const float4*)(crit + ((size_t)(b * NUM_EC + e)) * Q_DIM);
        const float4* wa  = (const float4*)W_align;

        float s = 0.f;
        #pragma unroll
        for (int i = 0; i < 16; ++i) {
            float4 c = row[q * 16 + i];
            float4 w = wa [q * 16 + i];
            s += c.x * w.x + c.y * w.y + c.z * w.z + c.w * w.w;
        }
        s += __shfl_xor_sync(0xffffffffu, s, 1);
        s += __shfl_xor_sync(0xffffffffu, s, 2);

        float* sm = sbuf;
        if (q == 0) sm[e] = s;
        __syncthreads();

        if (tid < 32) {
            float a  = sm[tid];
            float bb = sm[tid + 32];
            float m = fmaxf(a, bb);
            #pragma unroll
            for (int off = 16; off; off >>= 1)
                m = fmaxf(m, __shfl_xor_sync(0xffffffffu, m, off));
            float ea = expf(a - m);
            float eb = expf(bb - m);
            float ss = ea + eb;
            #pragma unroll
            for (int off = 16; off; off >>= 1)
                ss += __shfl_xor_sync(0xffffffffu, ss, off);
            float inv = 1.f / ss;
            g_att[b * NUM_EC + tid]      = ea * inv;
            g_att[b * NUM_EC + tid + 32] = eb * inv;
        }
        __syncthreads();
        pdl_trigger();

    } else {
        // ----- PE -----
        const int pg = bid - (C1_BLOCKS + ATT_BLOCKS);
        const int p0 = pg * PE_P_TILE;
        const int d  = tid;

        float* es = sbuf;                  // [PE_P_TILE][MEM_DIM]
        #pragma unroll
        for (int i = 0; i < PE_P_TILE; ++i)
            es[i * MEM_DIM + d] = ehr[(size_t)(p0 + i) * MEM_DIM + d];
        __syncthreads();

        float acc[PE_P_TILE];
        #pragma unroll
        for (int i = 0; i < PE_P_TILE; ++i) acc[i] = 0.f;

        const float* w = W_mlp + (size_t)Q_DIM * MLP_DIM + d;
        #pragma unroll 4
        for (int k = 0; k < MEM_DIM; ++k) {
            float wv = w[(size_t)k * MLP_DIM];
            #pragma unroll
            for (int i = 0; i < PE_P_TILE; ++i)
                acc[i] += es[i * MEM_DIM + k] * wv;
        }
        #pragma unroll
        for (int i = 0; i < PE_P_TILE; ++i)
            g_PE[(size_t)(p0 + i) * MLP_DIM + d] = acc[i];
        pdl_trigger();
    }
}

// ---------------------------------------------------------------------------
// Main (store-bound): out[b,p,e,d] = att[b,e]*(PC[b,e,d]+PE[p,d]) + b_mlp[d]
// 256-BIT STORES: thread = (e-row = tid>>5, v = tid&31 owning d[8v..8v+8)).
// Per e-iteration: 1 ld.global.nc.v8 (PC) + 4 st.global.cs.v8 (output).
// grid = 32 b x 32 p-groups (P_TILE=4), block = 256, PDL wait before
// touching prep outputs. Streaming (.cs) — R13 proved writeback regresses.
// ---------------------------------------------------------------------------
#define P_TILE 4
__global__ void __launch_bounds__(256) k_main(float* __restrict__ out,
                                              const float* __restrict__ b_mlp) {
    const int b   = blockIdx.x >> 5;
    const int pg  = blockIdx.x & 31;
    const int p0  = pg * P_TILE;
    const int tid = threadIdx.x;
    const int v   = tid & 31;          // 8-float lane in d
    const int er  = tid >> 5;          // e-row within iteration (0..7)
    const int dof = v * 8;             // float offset in d

    // Prologue on inputs only
    const f8 bm = ldg256(b_mlp + dof);
    const size_t base_f = ((size_t)b * BS2 + p0) * (NUM_EC * MLP_DIM);  // floats
    const size_t pstep  = (size_t)NUM_EC * MLP_DIM;                      // 16384

    pdl_wait();

    __shared__ float atts[NUM_EC];
    if (tid < NUM_EC) atts[tid] = g_att[b * NUM_EC + tid];
    __syncthreads();

    const f8 pe0 = ldg256(g_PE + (size_t)(p0 + 0) * MLP_DIM + dof);
    const f8 pe1 = ldg256(g_PE + (size_t)(p0 + 1) * MLP_DIM + dof);
    const f8 pe2 = ldg256(g_PE + (size_t)(p0 + 2) * MLP_DIM + dof);
    const f8 pe3 = ldg256(g_PE + (size_t)(p0 + 3) * MLP_DIM + dof);

    const float* pc = g_PC + (size_t)b * NUM_EC * MLP_DIM;

    #pragma unroll 4
    for (int k = 0; k < 8; ++k) {
        const int e = k * 8 + er;
        const float a = atts[e];
        const f8 c = ldg256(pc + (size_t)e * MLP_DIM + dof);
        const size_t obase = base_f + (size_t)e * MLP_DIM + dof;

        f8 r;
        // p0
        r.a.x = fmaf(a, c.a.x + pe0.a.x, bm.a.x); r.a.y = fmaf(a, c.a.y + pe0.a.y, bm.a.y);
        r.a.z = fmaf(a, c.a.z + pe0.a.z, bm.a.z); r.a.w = fmaf(a, c.a.w + pe0.a.w, bm.a.w);
        r.b.x = fmaf(a, c.b.x + pe0.b.x, bm.b.x); r.b.y = fmaf(a, c.b.y + pe0.b.y, bm.b.y);
        r.b.z = fmaf(a, c.b.z + pe0.b.z, bm.b.z); r.b.w = fmaf(a, c.b.w + pe0.b.w, bm.b.w);
        stg256_cs(out + obase + 0 * pstep, r);
        // p1
        r.a.x = fmaf(a, c.a.x + pe1.a.x, bm.a.x); r.a.y = fmaf(a, c.a.y + pe1.a.y, bm.a.y);
        r.a.z = fmaf(a, c.a.z + pe1.a.z, bm.a.z); r.a.w = fmaf(a, c.a.w + pe1.a.w, bm.a.w);
        r.b.x = fmaf(a, c.b.x + pe1.b.x, bm.b.x); r.b.y = fmaf(a, c.b.y + pe1.b.y, bm.b.y);
        r.b.z = fmaf(a, c.b.z + pe1.b.z, bm.b.z); r.b.w = fmaf(a, c.b.w + pe1.b.w, bm.b.w);
        stg256_cs(out + obase + 1 * pstep, r);
        // p2
        r.a.x = fmaf(a, c.a.x + pe2.a.x, bm.a.x); r.a.y = fmaf(a, c.a.y + pe2.a.y, bm.a.y);
        r.a.z = fmaf(a, c.a.z + pe2.a.z, bm.a.z); r.a.w = fmaf(a, c.a.w + pe2.a.w, bm.a.w);
        r.b.x = fmaf(a, c.b.x + pe2.b.x, bm.b.x); r.b.y = fmaf(a, c.b.y + pe2.b.y, bm.b.y);
        r.b.z = fmaf(a, c.b.z + pe2.b.z, bm.b.z); r.b.w = fmaf(a, c.b.w + pe2.b.w, bm.b.w);
        stg256_cs(out + obase + 2 * pstep, r);
        // p3
        r.a.x = fmaf(a, c.a.x + pe3.a.x, bm.a.x); r.a.y = fmaf(a, c.a.y + pe3.a.y, bm.a.y);
        r.a.z = fmaf(a, c.a.z + pe3.a.z, bm.a.z); r.a.w = fmaf(a, c.a.w + pe3.a.w, bm.a.w);
        r.b.x = fmaf(a, c.b.x + pe3.b.x, bm.b.x); r.b.y = fmaf(a, c.b.y + pe3.b.y, bm.b.y);
        r.b.z = fmaf(a, c.b.z + pe3.b.z, bm.b.z); r.b.w = fmaf(a, c.b.w + pe3.b.w, bm.b.w);
        stg256_cs(out + obase + 3 * pstep, r);
    }
}

// ---------------------------------------------------------------------------
// Inputs per metadata order:
// 0: ehr_vector (128*256)  1: criteria (32*64*256)  2: ec_mask (unused)
// 3: W_align (512)         4: b_align (unused, cancels in softmax)
// 5: W_mlp (512*256)       6: b_mlp (256)
// ---------------------------------------------------------------------------
extern "C" void kernel_launch(void* const* d_in, const int* in_sizes, int n_in,
                              void* d_out, int out_size) {
    const float* ehr     = (const float*)d_in[0];
    const float* crit    = (const float*)d_in[1];
    const float* W_align = (const float*)d_in[3];
    const float* W_mlp   = (const float*)d_in[5];
    const float* b_mlp   = (const float*)d_in[6];
    float* out = (float*)d_out;

    k_prep<<<C1_BLOCKS + ATT_BLOCKS + PE_BLOCKS, 256>>>(ehr, crit, W_align, W_mlp);

    cudaLaunchConfig_t cfg = {};
    cfg.gridDim  = dim3(BS1 * (BS2 / P_TILE), 1, 1);
    cfg.blockDim = dim3(256, 1, 1);
    cudaLaunchAttribute attrs[1];
    attrs[0].id = cudaLaunchAttributeProgrammaticStreamSerialization;
    attrs[0].val.programmaticStreamSerializationAllowed = 1;
    cfg.attrs = attrs;
    cfg.numAttrs = 1;
    cudaLaunchKernelEx(&cfg, k_main, out, (const float*)b_mlp);
}

// round 15
// speedup vs baseline: 1.0505x; 1.0505x over previous
#include <cuda_runtime.h>
#include <cuda_bf16.h>

// Problem constants
#define BS1 32
#define BS2 128
#define NUM_EC 64
#define MEM_DIM 256
#define MLP_DIM 256
#define Q_DIM 256           // 4 * CONV_DIM
#define HALF_B 16

// Scratch (device globals — allocation is forbidden)
__device__ float g_att[BS1 * NUM_EC];              // softmax_e(criteria·Wa_c)
__device__ float g_PC [BS1 * NUM_EC * MLP_DIM];    // raw criteria @ Wm_c
__device__ float g_PE [BS2 * MLP_DIM];             // ehr @ Wm_e

// ---- PDL primitives ----
__device__ __forceinline__ void pdl_trigger() {
    asm volatile("griddepcontrol.launch_dependents;");
}
__device__ __forceinline__ void pdl_wait() {
    asm volatile("griddepcontrol.wait;" ::: "memory");
}

// ---- packed f32x2 helpers ----
__device__ __forceinline__ unsigned long long pk2(float lo, float hi) {
    unsigned long long r;
    asm("mov.b64 %0, {%1, %2};" : "=l"(r)
        : "r"(__float_as_uint(lo)), "r"(__float_as_uint(hi)));
    return r;
}
__device__ __forceinline__ unsigned long long fma2(unsigned long long a,
                                                   unsigned long long b,
                                                   unsigned long long c) {
    unsigned long long d;
    asm("fma.rn.f32x2 %0, %1, %2, %3;" : "=l"(d) : "l"(a), "l"(b), "l"(c));
    return d;
}
__device__ __forceinline__ float2 upk2(unsigned long long v) {
    unsigned int lo, hi;
    asm("mov.b64 {%0, %1}, %2;" : "=r"(lo), "=r"(hi) : "l"(v));
    return make_float2(__uint_as_float(lo), __uint_as_float(hi));
}

// ---------------------------------------------------------------------------
// Prep kernel (R10 body, parameterized by b_base / half):
//   bids [0,128):   PC[b,e,d] for 16 b's (b = b_base + bid>>3)
//     Block = (b, e-tile of 16, d-half of 128); thread = (4d, 4e, k-half).
//     FMA2 paired across d; W float4 rows give packs free.
//   bids [128,160): att[b,:]  (only present in the first-half launch)
//   bids [160,192): PE[p,d]   (only present in the first-half launch)
// Every block fires pdl_trigger after its global writes.
// ---------------------------------------------------------------------------
#define C1H_BLOCKS  128
#define E_TILE      16
#define PE_P_TILE   4

__global__ void __launch_bounds__(256) k_prep(const float* __restrict__ ehr,
                                              const float* __restrict__ crit,
                                              const float* __restrict__ W_align,
                                              const float* __restrict__ W_mlp,
                                              int b_base) {
    __shared__ __align__(16) float sbuf[E_TILE * Q_DIM];   // 16 KB, reused
    const int bid = blockIdx.x;
    const int tid = threadIdx.x;

    if (bid < C1H_BLOCKS) {
        // ----- PC -----
        const int b   = b_base + (bid >> 3);
        const int et  = (bid >> 1) & 3;
        const int dh  = bid & 1;
        const int e0  = et * E_TILE;
        const int dg  = tid & 31;          // d-group (4 d each)
        const int es  = (tid >> 5) & 3;    // e-subtile (4 e each)
        const int kh  = tid >> 7;          // k-half (0/1)
        const int dloc = dg * 4;           // d within the 128-wide half
        const int d0  = dh * 128 + dloc;   // global d

        // load criteria[b, e0..e0+15, 0..255]  (1024 float4, 4 per thread)
        float4* cs = (float4*)sbuf;        // [E_TILE][64]
        const float4* src = (const float4*)(crit + (size_t)(b * NUM_EC + e0) * Q_DIM);
        #pragma unroll
        for (int i = 0; i < 4; ++i)
            cs[tid + i * 256] = src[tid + i * 256];
        __syncthreads();

        unsigned long long acc01[4], acc23[4];
        #pragma unroll
        for (int e = 0; e < 4; ++e) { acc01[e] = 0ull; acc23[e] = 0ull; }

        const int k4base = kh * 32;
        #pragma unroll 2
        for (int j = 0; j < 32; ++j) {
            const int k4 = k4base + j;
            const int k  = k4 * 4;
            const float4 w0 = *(const float4*)(W_mlp + (size_t)(k + 0) * MLP_DIM + d0);
            const float4 w1 = *(const float4*)(W_mlp + (size_t)(k + 1) * MLP_DIM + d0);
            const float4 w2 = *(const float4*)(W_mlp + (size_t)(k + 2) * MLP_DIM + d0);
            const float4 w3 = *(const float4*)(W_mlp + (size_t)(k + 3) * MLP_DIM + d0);
            const unsigned long long w0a = pk2(w0.x, w0.y), w0b = pk2(w0.z, w0.w);
            const unsigned long long w1a = pk2(w1.x, w1.y), w1b = pk2(w1.z, w1.w);
            const unsigned long long w2a = pk2(w2.x, w2.y), w2b = pk2(w2.z, w2.w);
            const unsigned long long w3a = pk2(w3.x, w3.y), w3b = pk2(w3.z, w3.w);
            #pragma unroll
            for (int e = 0; e < 4; ++e) {
                const float4 c = cs[(es * 4 + e) * 64 + k4];  // broadcast LDS.128
                unsigned long long cx = pk2(c.x, c.x);
                unsigned long long cy = pk2(c.y, c.y);
                unsigned long long cz = pk2(c.z, c.z);
                unsigned long long cw = pk2(c.w, c.w);
                acc01[e] = fma2(cx, w0a, acc01[e]);
                acc23[e] = fma2(cx, w0b, acc23[e]);
                acc01[e] = fma2(cy, w1a, acc01[e]);
                acc23[e] = fma2(cy, w1b, acc23[e]);
                acc01[e] = fma2(cz, w2a, acc01[e]);
                acc23[e] = fma2(cz, w2b, acc23[e]);
                acc01[e] = fma2(cw, w3a, acc01[e]);
                acc23[e] = fma2(cw, w3b, acc23[e]);
            }
        }
        __syncthreads();                   // criteria consumed; reuse as partials

        // partials: [2 kh][16 e][128 dloc]  = 16 KB
        float* part = sbuf;
        #pragma unroll
        for (int e = 0; e < 4; ++e) {
            const float2 a = upk2(acc01[e]);
            const float2 b2 = upk2(acc23[e]);
            float* p = part + ((kh * E_TILE + es * 4 + e) * 128 + dloc);
            p[0] = a.x; p[1] = a.y; p[2] = b2.x; p[3] = b2.y;
        }
        __syncthreads();

        // 2048 outputs, 256 threads -> 8 each (coalesced over dd)
        #pragma unroll
        for (int i = 0; i < 8; ++i) {
            const int idx = tid + i * 256;         // e*128 + dd
            const int e  = idx >> 7;
            const int dd = idx & 127;
            float v = part[e * 128 + dd] + part[(E_TILE + e) * 128 + dd];
            g_PC[((size_t)(b * NUM_EC + e0 + e)) * MLP_DIM + dh * 128 + dd] = v;
        }
        pdl_trigger();

    } else if (bid < C1H_BLOCKS + BS1) {
        // ----- att (all 32 b; only in the first-half launch) -----
        const int b = bid - C1H_BLOCKS;
        const int e = tid >> 2;
        const int q = tid & 3;

        const float4* row = (const float4*)(crit + ((size_t)(b * NUM_EC + e)) * Q_DIM);
        const float4* wa  = (const float4*)W_align;

        float s = 0.f;
        #pragma unroll
        for (int i = 0; i < 16; ++i) {
            float4 c = row[q * 16 + i];
            float4 w = wa [q * 16 + i];
            s += c.x * w.x + c.y * w.y + c.z * w.z + c.w * w.w;
        }
        s += __shfl_xor_sync(0xffffffffu, s, 1);
        s += __shfl_xor_sync(0xffffffffu, s, 2);

        float* sm = sbuf;
        if (q == 0) sm[e] = s;
        __syncthreads();

        if (tid < 32) {
            float a  = sm[tid];
            float bb = sm[tid + 32];
            float m = fmaxf(a, bb);
            #pragma unroll
            for (int off = 16; off; off >>= 1)
                m = fmaxf(m, __shfl_xor_sync(0xffffffffu, m, off));
            float ea = expf(a - m);
            float eb = expf(bb - m);
            float ss = ea + eb;
            #pragma unroll
            for (int off = 16; off; off >>= 1)
                ss += __shfl_xor_sync(0xffffffffu, ss, off);
            float inv = 1.f / ss;
            g_att[b * NUM_EC + tid]      = ea * inv;
            g_att[b * NUM_EC + tid + 32] = eb * inv;
        }
        __syncthreads();
        pdl_trigger();

    } else {
        // ----- PE (only in the first-half launch) -----
        const int pg = bid - (C1H_BLOCKS + BS1);
        const int p0 = pg * PE_P_TILE;
        const int d  = tid;

        float* es = sbuf;                  // [PE_P_TILE][MEM_DIM]
        #pragma unroll
        for (int i = 0; i < PE_P_TILE; ++i)
            es[i * MEM_DIM + d] = ehr[(size_t)(p0 + i) * MEM_DIM + d];
        __syncthreads();

        float acc[PE_P_TILE];
        #pragma unroll
        for (int i = 0; i < PE_P_TILE; ++i) acc[i] = 0.f;

        const float* w = W_mlp + (size_t)Q_DIM * MLP_DIM + d;
        #pragma unroll 4
        for (int k = 0; k < MEM_DIM; ++k) {
            float wv = w[(size_t)k * MLP_DIM];
            #pragma unroll
            for (int i = 0; i < PE_P_TILE; ++i)
                acc[i] += es[i * MEM_DIM + k] * wv;
        }
        #pragma unroll
        for (int i = 0; i < PE_P_TILE; ++i)
            g_PE[(size_t)(p0 + i) * MLP_DIM + d] = acc[i];
        pdl_trigger();
    }
}

// ---------------------------------------------------------------------------
// Main (store-bound; EXACT R10 body + b_base): 16 b's per launch, 512 blocks.
// out[b,p,e,d] = att[b,e] * (PC[b,e,d] + PE[p,d]) + b_mlp[d]
// pdl_trigger at START (releases the next prep launch to overlap stores),
// pdl_wait before touching this half's prep outputs.
// ---------------------------------------------------------------------------
#define P_TILE 4
__global__ void __launch_bounds__(256) k_main(float* __restrict__ out,
                                              const float* __restrict__ b_mlp,
                                              int b_base) {
    pdl_trigger();                       // release dependent launch immediately

    const int b   = b_base + (blockIdx.x >> 5);
    const int pg  = blockIdx.x & 31;
    const int p0  = pg * P_TILE;
    const int tid = threadIdx.x;
    const int v   = tid & 63;

    // Prologue on inputs only
    const float4 bm = __ldg((const float4*)b_mlp + v);
    float4* o = (float4*)out;
    const size_t base = (size_t)b * (BS2 * NUM_EC * (MLP_DIM / 4))
                      + (size_t)p0 * (NUM_EC * (MLP_DIM / 4));
    const int stride_p = NUM_EC * (MLP_DIM / 4);    // 4096 float4

    pdl_wait();                          // primary (this half's prep) complete

    __shared__ float atts[NUM_EC];
    if (tid < NUM_EC) atts[tid] = g_att[b * NUM_EC + tid];
    __syncthreads();

    const float4 pe0 = __ldg((const float4*)g_PE + (size_t)(p0 + 0) * (MLP_DIM / 4) + v);
    const float4 pe1 = __ldg((const float4*)g_PE + (size_t)(p0 + 1) * (MLP_DIM / 4) + v);
    const float4 pe2 = __ldg((const float4*)g_PE + (size_t)(p0 + 2) * (MLP_DIM / 4) + v);
    const float4 pe3 = __ldg((const float4*)g_PE + (size_t)(p0 + 3) * (MLP_DIM / 4) + v);

    const float4* pc = (const float4*)g_PC + (size_t)b * NUM_EC * (MLP_DIM / 4);

    #pragma unroll 4
    for (int k = 0; k < 16; ++k) {
        const int i = tid + k * 256;
        const float  a = atts[i >> 6];
        const float4 c = __ldg(&pc[i]);
        float4 r0, r1, r2, r3;
        r0.x = fmaf(a, c.x + pe0.x, bm.x); r0.y = fmaf(a, c.y + pe0.y, bm.y);
        r0.z = fmaf(a, c.z + pe0.z, bm.z); r0.w = fmaf(a, c.w + pe0.w, bm.w);
        r1.x = fmaf(a, c.x + pe1.x, bm.x); r1.y = fmaf(a, c.y + pe1.y, bm.y);
        r1.z = fmaf(a, c.z + pe1.z, bm.z); r1.w = fmaf(a, c.w + pe1.w, bm.w);
        r2.x = fmaf(a, c.x + pe2.x, bm.x); r2.y = fmaf(a, c.y + pe2.y, bm.y);
        r2.z = fmaf(a, c.z + pe2.z, bm.z); r2.w = fmaf(a, c.w + pe2.w, bm.w);
        r3.x = fmaf(a, c.x + pe3.x, bm.x); r3.y = fmaf(a, c.y + pe3.y, bm.y);
        r3.z = fmaf(a, c.z + pe3.z, bm.z); r3.w = fmaf(a, c.w + pe3.w, bm.w);
        __stcs(&o[base + 0 * stride_p + i], r0);
        __stcs(&o[base + 1 * stride_p + i], r1);
        __stcs(&o[base + 2 * stride_p + i], r2);
        __stcs(&o[base + 3 * stride_p + i], r3);
    }
}

// ---------------------------------------------------------------------------
// Launch: PDL pipeline  prep1 -> main1 -> prep2 -> main2.
// prep1 (plain): PC[b<16] + att + PE; triggers after writes.
// main1 (PDL):   stores b<16; triggers at start -> prep2 overlaps its stores.
// prep2 (PDL):   PC[b>=16]; inputs only, no wait; triggers after writes.
// main2 (PDL):   stores b>=16; waits prep2 completion.
// Next replay's prep1 is non-PDL -> serializes after main2 (replay-safe).
// Inputs per metadata order:
// 0: ehr_vector  1: criteria  2: ec_mask (unused)  3: W_align
// 4: b_align (unused, cancels in softmax)  5: W_mlp  6: b_mlp
// ---------------------------------------------------------------------------
extern "C" void kernel_launch(void* const* d_in, const int* in_sizes, int n_in,
                              void* d_out, int out_size) {
    const float* ehr     = (const float*)d_in[0];
    const float* crit    = (const float*)d_in[1];
    const float* W_align = (const float*)d_in[3];
    const float* W_mlp   = (const float*)d_in[5];
    const float* b_mlp   = (const float*)d_in[6];
    float* out = (float*)d_out;

    cudaLaunchAttribute pdl[1];
    pdl[0].id = cudaLaunchAttributeProgrammaticStreamSerialization;
    pdl[0].val.programmaticStreamSerializationAllowed = 1;

    // prep1: first-half PC + all att/PE (plain launch)
    k_prep<<<C1H_BLOCKS + BS1 + 32, 256>>>(ehr, crit, W_align, W_mlp, 0);

    // main1: stores b<16 (PDL secondary of prep1)
    {
        cudaLaunchConfig_t cfg = {};
        cfg.gridDim  = dim3(HALF_B * (BS2 / P_TILE), 1, 1);
        cfg.blockDim = dim3(256, 1, 1);
        cfg.attrs = pdl; cfg.numAttrs = 1;
        cudaLaunchKernelEx(&cfg, k_main, out, (const float*)b_mlp, 0);
    }
    // prep2: second-half PC (PDL secondary of main1 -> launches at main1 start)
    {
        cudaLaunchConfig_t cfg = {};
        cfg.gridDim  = dim3(C1H_BLOCKS, 1, 1);
        cfg.blockDim = dim3(256, 1, 1);
        cfg.attrs = pdl; cfg.numAttrs = 1;
        cudaLaunchKernelEx(&cfg, k_prep, ehr, crit, W_align, W_mlp, HALF_B);
    }
    // main2: stores b>=16 (PDL secondary of prep2)
    {
        cudaLaunchConfig_t cfg = {};
        cfg.gridDim  = dim3(HALF_B * (BS2 / P_TILE), 1, 1);
        cfg.blockDim = dim3(256, 1, 1);
        cfg.attrs = pdl; cfg.numAttrs = 1;
        cudaLaunchKernelEx(&cfg, k_main, out, (const float*)b_mlp, HALF_B);
    }
}

// round 16
// speedup vs baseline: 1.3175x; 1.2542x over previous
#include <cuda_runtime.h>
#include <cuda_bf16.h>

// Problem constants
#define BS1 32
#define BS2 128
#define NUM_EC 64
#define MEM_DIM 256
#define MLP_DIM 256
#define Q_DIM 256           // 4 * CONV_DIM

// Scratch (device globals — allocation is forbidden)
__device__ float g_att[BS1 * NUM_EC];              // softmax_e(criteria·Wa_c)
__device__ float g_PC [BS1 * NUM_EC * MLP_DIM];    // raw criteria @ Wm_c
__device__ float g_PE [BS2 * MLP_DIM];             // ehr @ Wm_e

// ---- PDL primitives ----
__device__ __forceinline__ void pdl_trigger() {
    asm volatile("griddepcontrol.launch_dependents;");
}
__device__ __forceinline__ void pdl_wait() {
    asm volatile("griddepcontrol.wait;" ::: "memory");
}

// ---- packed f32x2 helpers ----
__device__ __forceinline__ unsigned long long pk2(float lo, float hi) {
    unsigned long long r;
    asm("mov.b64 %0, {%1, %2};" : "=l"(r)
        : "r"(__float_as_uint(lo)), "r"(__float_as_uint(hi)));
    return r;
}
__device__ __forceinline__ unsigned long long fma2(unsigned long long a,
                                                   unsigned long long b,
                                                   unsigned long long c) {
    unsigned long long d;
    asm("fma.rn.f32x2 %0, %1, %2, %3;" : "=l"(d) : "l"(a), "l"(b), "l"(c));
    return d;
}
__device__ __forceinline__ float2 upk2(unsigned long long v) {
    unsigned int lo, hi;
    asm("mov.b64 {%0, %1}, %2;" : "=r"(lo), "=r"(hi) : "l"(v));
    return make_float2(__uint_as_float(lo), __uint_as_float(hi));
}

// ---------------------------------------------------------------------------
// Prep kernel, 320 blocks (measured best):
//   bids [0,256):   PC[b,e,d] = dot(criteria[b,e,:], Wm_c[:,d])
//     Block = (b, e-tile of 16, d-half of 128); thread = (4d, 4e, k-half).
//     FMA2 paired across d; W float4 rows give packs free.
//   bids [256,288): att[b,:] = softmax_e(criteria[b,e,:]·Wa_c)
//                   (logit_e[p] and b_align are constant over e -> cancel)
//   bids [288,320): PE[p,d] = dot(ehr[p,:], Wm_e[:,d])   (4 p / block)
// ---------------------------------------------------------------------------
#define C1_BLOCKS   256
#define ATT_BLOCKS  32
#define PE_BLOCKS   32
#define E_TILE      16
#define PE_P_TILE   4

__global__ void __launch_bounds__(256) k_prep(const float* __restrict__ ehr,
                                              const float* __restrict__ crit,
                                              const float* __restrict__ W_align,
                                              const float* __restrict__ W_mlp) {
    __shared__ __align__(16) float sbuf[E_TILE * Q_DIM];   // 16 KB, reused
    const int bid = blockIdx.x;
    const int tid = threadIdx.x;

    if (bid < C1_BLOCKS) {
        // ----- PC -----
        const int b   = bid >> 3;
        const int et  = (bid >> 1) & 3;
        const int dh  = bid & 1;
        const int e0  = et * E_TILE;
        const int dg  = tid & 31;          // d-group (4 d each)
        const int es  = (tid >> 5) & 3;    // e-subtile (4 e each)
        const int kh  = tid >> 7;          // k-half (0/1)
        const int dloc = dg * 4;           // d within the 128-wide half
        const int d0  = dh * 128 + dloc;   // global d

        // load criteria[b, e0..e0+15, 0..255]  (1024 float4, 4 per thread)
        float4* cs = (float4*)sbuf;        // [E_TILE][64]
        const float4* src = (const float4*)(crit + (size_t)(b * NUM_EC + e0) * Q_DIM);
        #pragma unroll
        for (int i = 0; i < 4; ++i)
            cs[tid + i * 256] = src[tid + i * 256];
        __syncthreads();

        // acc[4 e][4 d] as f32x2 pairs: (d0,d0+1) and (d0+2,d0+3)
        unsigned long long acc01[4], acc23[4];
        #pragma unroll
        for (int e = 0; e < 4; ++e) { acc01[e] = 0ull; acc23[e] = 0ull; }

        const int k4base = kh * 32;
        #pragma unroll 2
        for (int j = 0; j < 32; ++j) {
            const int k4 = k4base + j;
            const int k  = k4 * 4;
            const float4 w0 = *(const float4*)(W_mlp + (size_t)(k + 0) * MLP_DIM + d0);
            const float4 w1 = *(const float4*)(W_mlp + (size_t)(k + 1) * MLP_DIM + d0);
            const float4 w2 = *(const float4*)(W_mlp + (size_t)(k + 2) * MLP_DIM + d0);
            const float4 w3 = *(const float4*)(W_mlp + (size_t)(k + 3) * MLP_DIM + d0);
            const unsigned long long w0a = pk2(w0.x, w0.y), w0b = pk2(w0.z, w0.w);
            const unsigned long long w1a = pk2(w1.x, w1.y), w1b = pk2(w1.z, w1.w);
            const unsigned long long w2a = pk2(w2.x, w2.y), w2b = pk2(w2.z, w2.w);
            const unsigned long long w3a = pk2(w3.x, w3.y), w3b = pk2(w3.z, w3.w);
            #pragma unroll
            for (int e = 0; e < 4; ++e) {
                const float4 c = cs[(es * 4 + e) * 64 + k4];  // broadcast LDS.128
                unsigned long long cx = pk2(c.x, c.x);
                unsigned long long cy = pk2(c.y, c.y);
                unsigned long long cz = pk2(c.z, c.z);
                unsigned long long cw = pk2(c.w, c.w);
                acc01[e] = fma2(cx, w0a, acc01[e]);
                acc23[e] = fma2(cx, w0b, acc23[e]);
                acc01[e] = fma2(cy, w1a, acc01[e]);
                acc23[e] = fma2(cy, w1b, acc23[e]);
                acc01[e] = fma2(cz, w2a, acc01[e]);
                acc23[e] = fma2(cz, w2b, acc23[e]);
                acc01[e] = fma2(cw, w3a, acc01[e]);
                acc23[e] = fma2(cw, w3b, acc23[e]);
            }
        }
        __syncthreads();                   // criteria consumed; reuse as partials

        // partials: [2 kh][16 e][128 dloc]  = 16 KB
        float* part = sbuf;
        #pragma unroll
        for (int e = 0; e < 4; ++e) {
            const float2 a = upk2(acc01[e]);
            const float2 b2 = upk2(acc23[e]);
            float* p = part + ((kh * E_TILE + es * 4 + e) * 128 + dloc);
            p[0] = a.x; p[1] = a.y; p[2] = b2.x; p[3] = b2.y;
        }
        __syncthreads();

        // 2048 outputs, 256 threads -> 8 each (coalesced over dd)
        #pragma unroll
        for (int i = 0; i < 8; ++i) {
            const int idx = tid + i * 256;         // e*128 + dd
            const int e  = idx >> 7;
            const int dd = idx & 127;
            float v = part[e * 128 + dd] + part[(E_TILE + e) * 128 + dd];
            g_PC[((size_t)(b * NUM_EC + e0 + e)) * MLP_DIM + dh * 128 + dd] = v;
        }
        pdl_trigger();

    } else if (bid < C1_BLOCKS + ATT_BLOCKS) {
        // ----- att -----
        const int b = bid - C1_BLOCKS;
        const int e = tid >> 2;
        const int q = tid & 3;

        const float4* row = (const float4*)(crit + ((size_t)(b * NUM_EC + e)) * Q_DIM);
        const float4* wa  = (const float4*)W_align;

        float s = 0.f;
        #pragma unroll
        for (int i = 0; i < 16; ++i) {
            float4 c = row[q * 16 + i];
            float4 w = wa [q * 16 + i];
            s += c.x * w.x + c.y * w.y + c.z * w.z + c.w * w.w;
        }
        s += __shfl_xor_sync(0xffffffffu, s, 1);
        s += __shfl_xor_sync(0xffffffffu, s, 2);

        float* sm = sbuf;
        if (q == 0) sm[e] = s;
        __syncthreads();

        if (tid < 32) {
            float a  = sm[tid];
            float bb = sm[tid + 32];
            float m = fmaxf(a, bb);
            #pragma unroll
            for (int off = 16; off; off >>= 1)
                m = fmaxf(m, __shfl_xor_sync(0xffffffffu, m, off));
            float ea = expf(a - m);
            float eb = expf(bb - m);
            float ss = ea + eb;
            #pragma unroll
            for (int off = 16; off; off >>= 1)
                ss += __shfl_xor_sync(0xffffffffu, ss, off);
            float inv = 1.f / ss;
            g_att[b * NUM_EC + tid]      = ea * inv;
            g_att[b * NUM_EC + tid + 32] = eb * inv;
        }
        __syncthreads();
        pdl_trigger();

    } else {
        // ----- PE -----
        const int pg = bid - (C1_BLOCKS + ATT_BLOCKS);
        const int p0 = pg * PE_P_TILE;
        const int d  = tid;

        float* es = sbuf;                  // [PE_P_TILE][MEM_DIM]
        #pragma unroll
        for (int i = 0; i < PE_P_TILE; ++i)
            es[i * MEM_DIM + d] = ehr[(size_t)(p0 + i) * MEM_DIM + d];
        __syncthreads();

        float acc[PE_P_TILE];
        #pragma unroll
        for (int i = 0; i < PE_P_TILE; ++i) acc[i] = 0.f;

        const float* w = W_mlp + (size_t)Q_DIM * MLP_DIM + d;
        #pragma unroll 4
        for (int k = 0; k < MEM_DIM; ++k) {
            float wv = w[(size_t)k * MLP_DIM];
            #pragma unroll
            for (int i = 0; i < PE_P_TILE; ++i)
                acc[i] += es[i * MEM_DIM + k] * wv;
        }
        #pragma unroll
        for (int i = 0; i < PE_P_TILE; ++i)
            g_PE[(size_t)(p0 + i) * MLP_DIM + d] = acc[i];
        pdl_trigger();
    }
}

// ---------------------------------------------------------------------------
// Main (store-bound; measured best config — at the HBM write ceiling):
// out[b,p,e,d] = att[b,e] * (PC[b,e,d] + PE[p,d]) + b_mlp[d]
// grid = 32 b x 32 p-groups (P_TILE=4), block = 256, float4 + __stcs,
// PDL wait before touching prep outputs.
// ---------------------------------------------------------------------------
#define P_TILE 4
__global__ void __launch_bounds__(256) k_main(float* __restrict__ out,
                                              const float* __restrict__ b_mlp) {
    const int b   = blockIdx.x >> 5;
    const int pg  = blockIdx.x & 31;
    const int p0  = pg * P_TILE;
    const int tid = threadIdx.x;
    const int v   = tid & 63;

    // Prologue on inputs only (safe before the dependency resolves)
    const float4 bm = __ldg((const float4*)b_mlp + v);
    float4* o = (float4*)out;
    const size_t base = (size_t)b * (BS2 * NUM_EC * (MLP_DIM / 4))
                      + (size_t)p0 * (NUM_EC * (MLP_DIM / 4));
    const int stride_p = NUM_EC * (MLP_DIM / 4);    // 4096 float4

    pdl_wait();

    __shared__ float atts[NUM_EC];
    if (tid < NUM_EC) atts[tid] = g_att[b * NUM_EC + tid];
    __syncthreads();

    const float4 pe0 = __ldg((const float4*)g_PE + (size_t)(p0 + 0) * (MLP_DIM / 4) + v);
    const float4 pe1 = __ldg((const float4*)g_PE + (size_t)(p0 + 1) * (MLP_DIM / 4) + v);
    const float4 pe2 = __ldg((const float4*)g_PE + (size_t)(p0 + 2) * (MLP_DIM / 4) + v);
    const float4 pe3 = __ldg((const float4*)g_PE + (size_t)(p0 + 3) * (MLP_DIM / 4) + v);

    const float4* pc = (const float4*)g_PC + (size_t)b * NUM_EC * (MLP_DIM / 4);

    #pragma unroll 4
    for (int k = 0; k < 16; ++k) {
        const int i = tid + k * 256;
        const float  a = atts[i >> 6];
        const float4 c = __ldg(&pc[i]);
        float4 r0, r1, r2, r3;
        r0.x = fmaf(a, c.x + pe0.x, bm.x); r0.y = fmaf(a, c.y + pe0.y, bm.y);
        r0.z = fmaf(a, c.z + pe0.z, bm.z); r0.w = fmaf(a, c.w + pe0.w, bm.w);
        r1.x = fmaf(a, c.x + pe1.x, bm.x); r1.y = fmaf(a, c.y + pe1.y, bm.y);
        r1.z = fmaf(a, c.z + pe1.z, bm.z); r1.w = fmaf(a, c.w + pe1.w, bm.w);
        r2.x = fmaf(a, c.x + pe2.x, bm.x); r2.y = fmaf(a, c.y + pe2.y, bm.y);
        r2.z = fmaf(a, c.z + pe2.z, bm.z); r2.w = fmaf(a, c.w + pe2.w, bm.w);
        r3.x = fmaf(a, c.x + pe3.x, bm.x); r3.y = fmaf(a, c.y + pe3.y, bm.y);
        r3.z = fmaf(a, c.z + pe3.z, bm.z); r3.w = fmaf(a, c.w + pe3.w, bm.w);
        __stcs(&o[base + 0 * stride_p + i], r0);
        __stcs(&o[base + 1 * stride_p + i], r1);
        __stcs(&o[base + 2 * stride_p + i], r2);
        __stcs(&o[base + 3 * stride_p + i], r3);
    }
}

// ---------------------------------------------------------------------------
// Inputs per metadata order:
// 0: ehr_vector (128*256)  1: criteria (32*64*256)  2: ec_mask (unused)
// 3: W_align (512)         4: b_align (unused, cancels in softmax)
// 5: W_mlp (512*256)       6: b_mlp (256)
// ---------------------------------------------------------------------------
extern "C" void kernel_launch(void* const* d_in, const int* in_sizes, int n_in,
                              void* d_out, int out_size) {
    const float* ehr     = (const float*)d_in[0];
    const float* crit    = (const float*)d_in[1];
    const float* W_align = (const float*)d_in[3];
    const float* W_mlp   = (const float*)d_in[5];
    const float* b_mlp   = (const float*)d_in[6];
    float* out = (float*)d_out;

    k_prep<<<C1_BLOCKS + ATT_BLOCKS + PE_BLOCKS, 256>>>(ehr, crit, W_align, W_mlp);

    cudaLaunchConfig_t cfg = {};
    cfg.gridDim  = dim3(BS1 * (BS2 / P_TILE), 1, 1);
    cfg.blockDim = dim3(256, 1, 1);
    cudaLaunchAttribute attrs[1];
    attrs[0].id = cudaLaunchAttributeProgrammaticStreamSerialization;
    attrs[0].val.programmaticStreamSerializationAllowed = 1;
    cfg.attrs = attrs;
    cfg.numAttrs = 1;
    cudaLaunchKernelEx(&cfg, k_main, out, (const float*)b_mlp);
}